// round 15
// baseline (speedup 1.0000x reference)
#include <cuda_runtime.h>
#include <cuda_fp16.h>
#include <cstdint>

#define B_ 32
#define S_ 2048
#define K_ 512
#define V_ 512
#define H_ 256
#define NSPLIT 16

// ---------------- device scratch (allocation-free contract) ----------------
__device__ float g_c[B_ * H_];               // bk + bq + q@Wq.T per (b,h)
__device__ float g_logit[B_ * S_];
__device__ float g_part[B_ * NSPLIT * V_];
__device__ __align__(16) __half g_Wkh[H_ * K_];   // Wk fp16, [H][K] k-major
__device__ __align__(16) float  g_WkT[K_ * H_];   // Wk fp32 transposed [K][H]

// ---------------- helpers ----------------
static __device__ __forceinline__ uint32_t smem_u32(const void* p) {
    uint32_t a;
    asm("{ .reg .u64 t; cvta.to.shared.u64 t, %1; cvt.u32.u64 %0, t; }" : "=r"(a) : "l"(p));
    return a;
}
static __device__ __forceinline__ uint32_t pack_h2(float x, float y) {
    __half2 h = __floats2half2_rn(x, y);
    return *reinterpret_cast<uint32_t*>(&h);
}
static __device__ __forceinline__ void ldm_x4(uint32_t* r, uint32_t addr) {
    asm volatile("ldmatrix.sync.aligned.m8n8.x4.shared.b16 {%0,%1,%2,%3}, [%4];"
                 : "=r"(r[0]), "=r"(r[1]), "=r"(r[2]), "=r"(r[3]) : "r"(addr));
}
static __device__ __forceinline__ void mma16816(float* d, const uint32_t* a,
                                                uint32_t b0, uint32_t b1) {
    asm volatile(
        "mma.sync.aligned.m16n8k16.row.col.f32.f16.f16.f32 "
        "{%0,%1,%2,%3}, {%4,%5,%6,%7}, {%8,%9}, {%0,%1,%2,%3};"
        : "+f"(d[0]), "+f"(d[1]), "+f"(d[2]), "+f"(d[3])
        : "r"(a[0]), "r"(a[1]), "r"(a[2]), "r"(a[3]), "r"(b0), "r"(b1));
}
// packed f32x2 (FFMA2 path)
static __device__ __forceinline__ unsigned long long pack2(float x, float y) {
    unsigned long long r;
    asm("mov.b64 %0, {%1, %2};" : "=l"(r) : "f"(x), "f"(y));
    return r;
}
static __device__ __forceinline__ unsigned long long fma2(unsigned long long a,
                                                          unsigned long long b,
                                                          unsigned long long c) {
    unsigned long long d;
    asm("fma.rn.f32x2 %0, %1, %2, %3;" : "=l"(d) : "l"(a), "l"(b), "l"(c));
    return d;
}
static __device__ __forceinline__ float2 unpack2(unsigned long long v) {
    float2 f;
    asm("mov.b64 {%0, %1}, %2;" : "=f"(f.x), "=f"(f.y) : "l"(v));
    return f;
}
#define CP16(dst, src) \
    asm volatile("cp.async.cg.shared.global [%0], [%1], 16;" :: "r"(dst), "l"(src) : "memory")
#define CPCOMMIT() asm volatile("cp.async.commit_group;" ::: "memory")
#define CPWAIT0()  asm volatile("cp.async.wait_group 0;" ::: "memory")

// ---------------- 0. prep: Wk->fp16 + fp32 transpose; hq fused ----------------
__global__ void prep_kernel(const float* __restrict__ Wk, const float* __restrict__ q,
                            const float* __restrict__ Wq, const float* __restrict__ bq,
                            const float* __restrict__ bk) {
    if (blockIdx.x < 512) {
        int idx = blockIdx.x * 256 + threadIdx.x;   // < 131072
        float w = Wk[idx];
        g_Wkh[idx] = __float2half_rn(w);
        int h = idx >> 9, k = idx & 511;
        g_WkT[k * H_ + h] = w;
    } else {
        __shared__ float sq[K_];
        int b = blockIdx.x - 512, h = threadIdx.x;
        for (int i = h; i < K_; i += 256) sq[i] = q[b * K_ + i];
        __syncthreads();
        const float* w = Wq + h * K_;
        float acc = 0.f;
#pragma unroll 8
        for (int kk = 0; kk < K_; kk++) acc = fmaf(sq[kk], w[kk], acc);
        g_c[b * H_ + h] = acc + bq[h] + bk[h];
    }
}

// ---------------- 2. hybrid HMMA + FFMA2 GEMM + fused tanh/Wo epilogue ----------
// CTA: MT=128 rows (one b). Rows 0..95: 12 HMMA warps (3M x 4N, warp tile 32x64).
// Rows 96..127: 4 FFMA2 warps (fp32 path, own fp32 A/B smem tiles).
// Per SMSP: 3 tensor warps + 1 fma warp -> both pipes busy concurrently.
#define MT 128
#define BK 32
#define NC (K_ / BK)       // 16 chunks
#define THREADS 512
#define ROWB 80            // fp16 padded row: 32 fp16 = 64 B + 16 B pad
#define APAD 36            // fp32 A tile row pad (words)

#define OFF_C    0
#define OFF_WO   1024
#define OFF_RED  2048      // tensor red: 96*4 floats = 1536 B
#define OFF_RED2 3584      // fma red: 32*17 floats = 2176 B (ends 5760)
#define OFF_T    6144
#define T_A16 0            // 96 rows * 80 B   = 7680
#define T_B16 7680         // 256 rows * 80 B  = 20480
#define T_A32 28160        // 32 kk * 36 w * 4 = 4608
#define T_B32 32768        // 32 kk * 256 * 4  = 32768
#define STAGE 65536
#define SMEM_TOTAL (OFF_T + 2 * STAGE)   // 137216 B -> 1 CTA/SM

__global__ void __launch_bounds__(THREADS, 1) logit_kernel(const float* __restrict__ kten,
                                                           const float* __restrict__ Wo) {
    extern __shared__ char smem[];
    const uint32_t sbase = smem_u32(smem);
    const int tid  = threadIdx.x;
    const int wid  = tid >> 5;
    const int lane = tid & 31;
    const int b  = blockIdx.y;
    const int s0 = blockIdx.x * MT;

    if (tid < H_) {
        ((float*)(smem + OFF_C))[tid]  = g_c[b * H_ + tid];
        ((float*)(smem + OFF_WO))[tid] = Wo[tid];
    }

    const float* abase = kten + ((size_t)s0 * B_ + b) * K_;  // row stride B_*K_

    // tensor-warp addressing (wid < 12): mw = wid/4 in 0..2, nw = wid%4
    const int mw = wid >> 2;
    const int nw = wid & 3;
    const uint32_t fragLane = (uint32_t)(lane & 15) * ROWB + (uint32_t)(lane >> 4) * 16u;
    const uint32_t aWarp = (uint32_t)mw * 32u * ROWB;
    const uint32_t bWarp = (uint32_t)nw * 64u * ROWB;

    // fma-warp addressing (wid >= 12): ftid 0..127; tx 16 cols, ty 4 rows
    const int ftid = tid - 384;
    const int tx = (ftid >> 3) & 15;   // 0..15
    const int ty = ftid & 7;           // 0..7

    float acc[2][8][4];
#pragma unroll
    for (int mt = 0; mt < 2; ++mt)
#pragma unroll
        for (int nt = 0; nt < 8; ++nt)
#pragma unroll
            for (int r = 0; r < 4; ++r) acc[mt][nt][r] = 0.f;

    unsigned long long facc[4][8];
#pragma unroll
    for (int r = 0; r < 4; ++r)
#pragma unroll
        for (int j = 0; j < 8; ++j) facc[r][j] = 0ull;

    float4 areg[2];

    // ---- loaders (all 512 threads) ----
#define LDG_A(c)                                                                     \
    {                                                                                \
        const int k0 = (c) * BK;                                                     \
        _Pragma("unroll")                                                            \
        for (int i = 0; i < 2; ++i) {                                                \
            int idx = tid + i * 512;                                                 \
            int row = idx >> 3, c4 = idx & 7;                                        \
            areg[i] = *(const float4*)(abase + (size_t)row * (B_ * K_) + k0 + c4 * 4); \
        }                                                                            \
    }
#define STS_A(stg)                                                                   \
    {                                                                                \
        char* sb = smem + OFF_T + (stg) * STAGE;                                     \
        _Pragma("unroll")                                                            \
        for (int i = 0; i < 2; ++i) {                                                \
            int idx = tid + i * 512;                                                 \
            int row = idx >> 3, c4 = idx & 7;                                        \
            float4 v = areg[i];                                                      \
            if (row < 96) {                                                          \
                uint32_t off = (uint32_t)row * ROWB + (uint32_t)c4 * 8u;             \
                *(uint2*)(sb + T_A16 + off) = make_uint2(pack_h2(v.x, v.y), pack_h2(v.z, v.w)); \
            } else {                                                                 \
                int r32 = row - 96;                                                  \
                float* dst = (float*)(sb + T_A32);                                   \
                dst[(c4 * 4 + 0) * APAD + r32] = v.x;                                \
                dst[(c4 * 4 + 1) * APAD + r32] = v.y;                                \
                dst[(c4 * 4 + 2) * APAD + r32] = v.z;                                \
                dst[(c4 * 4 + 3) * APAD + r32] = v.w;                                \
            }                                                                        \
        }                                                                            \
    }
#define CPA_B(c, stg)                                                                \
    {                                                                                \
        const int k0 = (c) * BK;                                                     \
        uint32_t sb = sbase + OFF_T + (stg) * STAGE;                                 \
        _Pragma("unroll")                                                            \
        for (int i = 0; i < 2; ++i) {                                                \
            int idx = tid + i * 512;         /* 1024 x 16B: fp16 B */                \
            int row = idx >> 2, c8 = idx & 3;                                        \
            uint32_t off = (uint32_t)row * ROWB + (uint32_t)c8 * 16u;                \
            CP16(sb + T_B16 + off, (const char*)(g_Wkh + row * K_ + k0 + c8 * 8));   \
        }                                                                            \
        _Pragma("unroll")                                                            \
        for (int i = 0; i < 4; ++i) {                                                \
            int idx = tid + i * 512;         /* 2048 x 16B: fp32 B [kk][h] */        \
            int kk = idx >> 6, rem = idx & 63;                                       \
            CP16(sb + T_B32 + kk * 1024 + rem * 16,                                  \
                 (const char*)(g_WkT + (k0 + kk) * H_ + rem * 4));                   \
        }                                                                            \
        CPCOMMIT();                                                                  \
    }

    // prologue: chunk 0 into stage 0
    LDG_A(0);
    CPA_B(0, 0);
    STS_A(0);
    CPWAIT0();
    __syncthreads();

#pragma unroll 1
    for (int c = 0; c < NC; ++c) {
        const int st = c & 1;
        if (c + 1 < NC) {
            LDG_A(c + 1);
            CPA_B(c + 1, st ^ 1);
        }
        if (wid < 12) {
            // ---- tensor path: 96 rows x 256 cols ----
            const uint32_t sb = sbase + OFF_T + (uint32_t)st * STAGE;
#pragma unroll
            for (int ks = 0; ks < 2; ++ks) {
                uint32_t ah[2][4];
                const uint32_t aoff = sb + T_A16 + aWarp + fragLane + (uint32_t)ks * 32u;
#pragma unroll
                for (int mt = 0; mt < 2; ++mt)
                    ldm_x4(ah[mt], aoff + (uint32_t)mt * (16u * ROWB));
                const uint32_t boff = sb + T_B16 + bWarp + fragLane + (uint32_t)ks * 32u;
#pragma unroll
                for (int ntp = 0; ntp < 4; ++ntp) {
                    uint32_t bh[4];
                    ldm_x4(bh, boff + (uint32_t)ntp * (16u * ROWB));
                    mma16816(acc[0][ntp * 2],     ah[0], bh[0], bh[2]);
                    mma16816(acc[1][ntp * 2],     ah[1], bh[0], bh[2]);
                    mma16816(acc[0][ntp * 2 + 1], ah[0], bh[1], bh[3]);
                    mma16816(acc[1][ntp * 2 + 1], ah[1], bh[1], bh[3]);
                }
            }
        } else {
            // ---- fma path: rows 96..127, fp32 ----
            const char* sb = smem + OFF_T + (size_t)st * STAGE;
            const float* sA32 = (const float*)(sb + T_A32);
            const char*  sB32 = sb + T_B32;
#pragma unroll 8
            for (int kk = 0; kk < BK; ++kk) {
                float4 av = *(const float4*)(sA32 + kk * APAD + ty * 4);
                unsigned long long a0 = pack2(av.x, av.x);
                unsigned long long a1 = pack2(av.y, av.y);
                unsigned long long a2 = pack2(av.z, av.z);
                unsigned long long a3 = pack2(av.w, av.w);
                const ulonglong2* bp = (const ulonglong2*)(sB32 + kk * 1024 + tx * 64);
                ulonglong2 u0 = bp[0], u1 = bp[1], u2 = bp[2], u3 = bp[3];
                unsigned long long bv[8] = {u0.x, u0.y, u1.x, u1.y, u2.x, u2.y, u3.x, u3.y};
#pragma unroll
                for (int j = 0; j < 8; ++j) {
                    facc[0][j] = fma2(a0, bv[j], facc[0][j]);
                    facc[1][j] = fma2(a1, bv[j], facc[1][j]);
                    facc[2][j] = fma2(a2, bv[j], facc[2][j]);
                    facc[3][j] = fma2(a3, bv[j], facc[3][j]);
                }
            }
        }
        if (c + 1 < NC) {
            STS_A((c + 1) & 1);
            CPWAIT0();
            __syncthreads();
        }
    }

    // ---- epilogue: tanh(h + c) dot Wo, reduce ----
    {
        const float* sC = (const float*)(smem + OFF_C);
        const float* sW = (const float*)(smem + OFF_WO);
        float* red  = (float*)(smem + OFF_RED);   // [96][4]
        float* red2 = (float*)(smem + OFF_RED2);  // [32][17]
        __syncthreads();
#define FTANH(x) ({ float _x = (x); float _a = fabsf(_x);                        \
                    float _t = 1.f - __fdividef(2.f, __expf(_a + _a) + 1.f);     \
                    copysignf(_t, _x); })
        if (wid < 12) {
#pragma unroll
            for (int mt = 0; mt < 2; ++mt) {
                float sl = 0.f, sh = 0.f;
#pragma unroll
                for (int nt = 0; nt < 8; ++nt) {
                    int h0 = nw * 64 + nt * 8 + (lane & 3) * 2;
                    float c0 = sC[h0], c1 = sC[h0 + 1];
                    float w0 = sW[h0], w1 = sW[h0 + 1];
                    sl = fmaf(FTANH(acc[mt][nt][0] + c0), w0, sl);
                    sl = fmaf(FTANH(acc[mt][nt][1] + c1), w1, sl);
                    sh = fmaf(FTANH(acc[mt][nt][2] + c0), w0, sh);
                    sh = fmaf(FTANH(acc[mt][nt][3] + c1), w1, sh);
                }
                sl += __shfl_xor_sync(0xffffffffu, sl, 1);
                sl += __shfl_xor_sync(0xffffffffu, sl, 2);
                sh += __shfl_xor_sync(0xffffffffu, sh, 1);
                sh += __shfl_xor_sync(0xffffffffu, sh, 2);
                if ((lane & 3) == 0) {
                    int r = mw * 32 + mt * 16 + (lane >> 2);
                    red[r * 4 + nw]       = sl;
                    red[(r + 8) * 4 + nw] = sh;
                }
            }
        } else {
#pragma unroll
            for (int r = 0; r < 4; ++r) {
                float p = 0.f;
#pragma unroll
                for (int j = 0; j < 8; ++j) {
                    float2 hv = unpack2(facc[r][j]);
                    int h0 = tx * 16 + 2 * j;
                    p = fmaf(FTANH(hv.x + sC[h0]),     sW[h0],     p);
                    p = fmaf(FTANH(hv.y + sC[h0 + 1]), sW[h0 + 1], p);
                }
                red2[(ty * 4 + r) * 17 + tx] = p;
            }
        }
#undef FTANH
        __syncthreads();
        if (tid < 96) {
            float s = red[tid * 4] + red[tid * 4 + 1] + red[tid * 4 + 2] + red[tid * 4 + 3];
            g_logit[b * S_ + s0 + tid] = s;
        } else if (tid < MT) {
            int r = tid - 96;
            float s = 0.f;
#pragma unroll
            for (int t = 0; t < 16; ++t) s += red2[r * 17 + t];
            g_logit[b * S_ + s0 + tid] = s;  // rows 96..127
        }
        // bo omitted: softmax shift-invariant
    }
}

// ---------------- 3. softmax over S per batch -> p (1024 threads) ----------------
__global__ void softmax_kernel(float* __restrict__ p_out) {
    __shared__ float sred[32];
    __shared__ float sbcast;
    const int b = blockIdx.x, tid = threadIdx.x;

    float mx = -1e30f;
    for (int s = tid; s < S_; s += 1024) mx = fmaxf(mx, g_logit[b * S_ + s]);
#pragma unroll
    for (int o = 16; o; o >>= 1) mx = fmaxf(mx, __shfl_xor_sync(0xffffffffu, mx, o));
    if ((tid & 31) == 0) sred[tid >> 5] = mx;
    __syncthreads();
    if (tid < 32) {
        float v = sred[tid];
#pragma unroll
        for (int o = 16; o; o >>= 1) v = fmaxf(v, __shfl_xor_sync(0xffffffffu, v, o));
        if (tid == 0) sbcast = v;
    }
    __syncthreads();
    mx = sbcast;
    __syncthreads();

    float sum = 0.f;
    for (int s = tid; s < S_; s += 1024) {
        float e = expf(g_logit[b * S_ + s] - mx);
        g_logit[b * S_ + s] = e;
        sum += e;
    }
#pragma unroll
    for (int o = 16; o; o >>= 1) sum += __shfl_xor_sync(0xffffffffu, sum, o);
    if ((tid & 31) == 0) sred[tid >> 5] = sum;
    __syncthreads();
    if (tid < 32) {
        float v = sred[tid];
#pragma unroll
        for (int o = 16; o; o >>= 1) v += __shfl_xor_sync(0xffffffffu, v, o);
        if (tid == 0) sbcast = v;
    }
    __syncthreads();
    float inv = 1.f / sbcast;
    for (int s = tid; s < S_; s += 1024) p_out[b * S_ + s] = g_logit[b * S_ + s] * inv;
}

// ---------------- 4. out[b,:] = sum_s p[b,s] * v[s,b,:] ----------------
__global__ void wsum_kernel(const float* __restrict__ v, const float* __restrict__ p) {
    const int b = blockIdx.y, sp = blockIdx.x, tid = threadIdx.x;
    const int col = tid * 2;
    const int SCH = S_ / NSPLIT;
    const int s0 = sp * SCH;
    const float* pb = p + b * S_;
    float2 acc = make_float2(0.f, 0.f);
#pragma unroll 4
    for (int i = 0; i < SCH; i++) {
        int s = s0 + i;
        float pv = __ldg(pb + s);
        float2 vv = *(const float2*)(v + ((size_t)s * B_ + b) * V_ + col);
        acc.x = fmaf(pv, vv.x, acc.x);
        acc.y = fmaf(pv, vv.y, acc.y);
    }
    float* dst = g_part + (b * NSPLIT + sp) * V_ + col;
    dst[0] = acc.x;
    dst[1] = acc.y;
}

__global__ void reduce_out(float* __restrict__ out) {
    const int b = blockIdx.x, tid = threadIdx.x;
    float s = 0.f;
#pragma unroll
    for (int i = 0; i < NSPLIT; i++) s += g_part[(b * NSPLIT + i) * V_ + tid];
    out[b * V_ + tid] = s;
}

// ---------------- launch ----------------
extern "C" void kernel_launch(void* const* d_in, const int* in_sizes, int n_in,
                              void* d_out, int out_size) {
    const float* q  = (const float*)d_in[0];
    const float* k  = (const float*)d_in[1];
    const float* v  = (const float*)d_in[2];
    const float* Wk = (const float*)d_in[3];
    const float* bk = (const float*)d_in[4];
    const float* Wq = (const float*)d_in[5];
    const float* bq = (const float*)d_in[6];
    const float* Wo = (const float*)d_in[7];
    // d_in[8] = bo: irrelevant under softmax shift invariance

    float* out = (float*)d_out;    // out[1,B,V]
    float* p   = out + B_ * V_;    // p[B,S]

    cudaFuncSetAttribute(logit_kernel, cudaFuncAttributeMaxDynamicSharedMemorySize, SMEM_TOTAL);

    prep_kernel<<<512 + B_, 256>>>(Wk, q, Wq, bq, bk);
    logit_kernel<<<dim3(S_ / MT, B_), THREADS, SMEM_TOTAL>>>(k, Wo);
    softmax_kernel<<<B_, 1024>>>(p);
    wsum_kernel<<<dim3(NSPLIT, B_), 256>>>(v, p);
    reduce_out<<<B_, V_>>>(out);
}

// round 17
// speedup vs baseline: 2.6762x; 2.6762x over previous
#include <cuda_runtime.h>
#include <cuda_fp16.h>
#include <cstdint>

#define B_ 32
#define S_ 2048
#define K_ 512
#define V_ 512
#define H_ 256
#define NSPLIT 32

// ---------------- device scratch (allocation-free contract) ----------------
__device__ float g_c[B_ * H_];               // bk + bq + q@Wq.T per (b,h)
__device__ float g_logit[B_ * S_];
__device__ float g_part[B_ * NSPLIT * V_];
__device__ __align__(16) __half g_Wkh[H_ * K_];   // Wk fp16, [H][K] k-major

// ---------------- helpers ----------------
static __device__ __forceinline__ uint32_t smem_u32(const void* p) {
    uint32_t a;
    asm("{ .reg .u64 t; cvta.to.shared.u64 t, %1; cvt.u32.u64 %0, t; }" : "=r"(a) : "l"(p));
    return a;
}
static __device__ __forceinline__ uint32_t pack_h2(float x, float y) {
    __half2 h = __floats2half2_rn(x, y);
    return *reinterpret_cast<uint32_t*>(&h);
}
static __device__ __forceinline__ void ldm_x4(uint32_t* r, uint32_t addr) {
    asm volatile("ldmatrix.sync.aligned.m8n8.x4.shared.b16 {%0,%1,%2,%3}, [%4];"
                 : "=r"(r[0]), "=r"(r[1]), "=r"(r[2]), "=r"(r[3]) : "r"(addr));
}
static __device__ __forceinline__ void mma16816(float* d, const uint32_t* a,
                                                uint32_t b0, uint32_t b1) {
    asm volatile(
        "mma.sync.aligned.m16n8k16.row.col.f32.f16.f16.f32 "
        "{%0,%1,%2,%3}, {%4,%5,%6,%7}, {%8,%9}, {%0,%1,%2,%3};"
        : "+f"(d[0]), "+f"(d[1]), "+f"(d[2]), "+f"(d[3])
        : "r"(a[0]), "r"(a[1]), "r"(a[2]), "r"(a[3]), "r"(b0), "r"(b1));
}
#define CP16(dst, src) \
    asm volatile("cp.async.cg.shared.global [%0], [%1], 16;" :: "r"(dst), "l"(src) : "memory")
#define CPCOMMIT() asm volatile("cp.async.commit_group;" ::: "memory")
#define CPWAIT0()  asm volatile("cp.async.wait_group 0;" ::: "memory")

// ---------------- 0. prep: Wk->fp16; hq fused ----------------
__global__ void prep_kernel(const float* __restrict__ Wk, const float* __restrict__ q,
                            const float* __restrict__ Wq, const float* __restrict__ bq,
                            const float* __restrict__ bk) {
    if (blockIdx.x < 512) {
        int idx = blockIdx.x * 256 + threadIdx.x;   // < 131072
        g_Wkh[idx] = __float2half_rn(Wk[idx]);
    } else {
        __shared__ float sq[K_];
        int b = blockIdx.x - 512, h = threadIdx.x;
        for (int i = h; i < K_; i += 256) sq[i] = q[b * K_ + i];
        __syncthreads();
        const float* w = Wq + h * K_;
        float acc = 0.f;
#pragma unroll 8
        for (int kk = 0; kk < K_; kk++) acc = fmaf(sq[kk], w[kk], acc);
        g_c[b * H_ + h] = acc + bq[h] + bk[h];
    }
}

// ---------------- 2. single-pass fp16 HMMA GEMM + fused tanh/Wo epilogue ----------
// CTA: M=64 (one b, 64 s) x N=256 (all H). K chunks of 32, double-buffered.
// 8 warps as 2(M) x 4(N); warp tile 32x64; acc fp32 in registers. 2 CTAs/SM.
#define MT 64
#define BK 32
#define NC (K_ / BK)       // 16 chunks
#define THREADS 256
#define ROWB 80            // padded row: 32 fp16 = 64 B data + 16 B pad

#define OFF_C   0
#define OFF_WO  1024
#define OFF_RED 2048
#define OFF_T   4096
#define T_A  0
#define T_B  5120          // A tile: 64 rows * 80 B
#define STAGE 25600        // A (5120) + B (256*80 = 20480)
#define SMEM_TOTAL (OFF_T + 2 * STAGE)   // 55296 B -> 2 CTAs/SM

__global__ void __launch_bounds__(THREADS, 2) logit_kernel(const float* __restrict__ kten,
                                                           const float* __restrict__ Wo) {
    extern __shared__ char smem[];
    const uint32_t sbase = smem_u32(smem);
    const int tid  = threadIdx.x;
    const int wid  = tid >> 5;
    const int lane = tid & 31;
    const int mw = wid >> 2;      // 0..1 (M groups of 32 rows)
    const int nw = wid & 3;       // 0..3 (N groups of 64 cols)
    const int b  = blockIdx.y;
    const int s0 = blockIdx.x * MT;

    if (tid < H_) {
        ((float*)(smem + OFF_C))[tid]  = g_c[b * H_ + tid];
        ((float*)(smem + OFF_WO))[tid] = Wo[tid];
    }

    const float* abase = kten + ((size_t)s0 * B_ + b) * K_;  // row stride B_*K_

    const uint32_t fragLane = (uint32_t)(lane & 15) * ROWB + (uint32_t)(lane >> 4) * 16u;
    const uint32_t aWarp = (uint32_t)mw * 32u * ROWB;
    const uint32_t bWarp = (uint32_t)nw * 64u * ROWB;

    float acc[2][8][4];
#pragma unroll
    for (int mt = 0; mt < 2; ++mt)
#pragma unroll
        for (int nt = 0; nt < 8; ++nt)
#pragma unroll
            for (int r = 0; r < 4; ++r) acc[mt][nt][r] = 0.f;

    float4 areg[2];

#define LDG_A(c)                                                                     \
    {                                                                                \
        const int k0 = (c) * BK;                                                     \
        _Pragma("unroll")                                                            \
        for (int i = 0; i < 2; ++i) {                                                \
            int idx = tid + i * 256;                                                 \
            int row = idx >> 3, c4 = idx & 7;                                        \
            areg[i] = *(const float4*)(abase + (size_t)row * (B_ * K_) + k0 + c4 * 4); \
        }                                                                            \
    }
#define STS_A(stg)                                                                   \
    {                                                                                \
        char* sb = smem + OFF_T + (stg) * STAGE;                                     \
        _Pragma("unroll")                                                            \
        for (int i = 0; i < 2; ++i) {                                                \
            int idx = tid + i * 256;                                                 \
            int row = idx >> 3, c4 = idx & 7;                                        \
            float4 v = areg[i];                                                      \
            uint32_t off = (uint32_t)row * ROWB + (uint32_t)c4 * 8u;                 \
            *(uint2*)(sb + T_A + off) = make_uint2(pack_h2(v.x, v.y), pack_h2(v.z, v.w)); \
        }                                                                            \
    }
#define CPA_B(c, stg)                                                                \
    {                                                                                \
        const int k0 = (c) * BK;                                                     \
        uint32_t sb = sbase + OFF_T + (stg) * STAGE;                                 \
        _Pragma("unroll")                                                            \
        for (int i = 0; i < 4; ++i) {                                                \
            int idx = tid + i * 256;                                                 \
            int row = idx >> 2, c8 = idx & 3;                                        \
            uint32_t off = (uint32_t)row * ROWB + (uint32_t)c8 * 16u;                \
            CP16(sb + T_B + off, (const char*)(g_Wkh + row * K_ + k0 + c8 * 8));     \
        }                                                                            \
        CPCOMMIT();                                                                  \
    }

    LDG_A(0);
    CPA_B(0, 0);
    STS_A(0);
    CPWAIT0();
    __syncthreads();

#pragma unroll 1
    for (int c = 0; c < NC; ++c) {
        const int st = c & 1;
        if (c + 1 < NC) {
            LDG_A(c + 1);
            CPA_B(c + 1, st ^ 1);
        }
        {
            const uint32_t sb = sbase + OFF_T + (uint32_t)st * STAGE;
#pragma unroll
            for (int ks = 0; ks < 2; ++ks) {
                uint32_t ah[2][4];
                const uint32_t aoff = sb + T_A + aWarp + fragLane + (uint32_t)ks * 32u;
#pragma unroll
                for (int mt = 0; mt < 2; ++mt)
                    ldm_x4(ah[mt], aoff + (uint32_t)mt * (16u * ROWB));
                const uint32_t boff = sb + T_B + bWarp + fragLane + (uint32_t)ks * 32u;
#pragma unroll
                for (int ntp = 0; ntp < 4; ++ntp) {
                    uint32_t bh[4];
                    ldm_x4(bh, boff + (uint32_t)ntp * (16u * ROWB));
                    mma16816(acc[0][ntp * 2],     ah[0], bh[0], bh[2]);
                    mma16816(acc[1][ntp * 2],     ah[1], bh[0], bh[2]);
                    mma16816(acc[0][ntp * 2 + 1], ah[0], bh[1], bh[3]);
                    mma16816(acc[1][ntp * 2 + 1], ah[1], bh[1], bh[3]);
                }
            }
        }
        if (c + 1 < NC) {
            STS_A((c + 1) & 1);
            CPWAIT0();
            __syncthreads();
        }
    }

    // ---- epilogue: tanh(h + c) dot Wo, reduce ----
    {
        const float* sC = (const float*)(smem + OFF_C);
        const float* sW = (const float*)(smem + OFF_WO);
        float* red = (float*)(smem + OFF_RED);
        __syncthreads();
#pragma unroll
        for (int mt = 0; mt < 2; ++mt) {
            float sl = 0.f, sh = 0.f;
#pragma unroll
            for (int nt = 0; nt < 8; ++nt) {
                int h0 = nw * 64 + nt * 8 + (lane & 3) * 2;
                float c0 = sC[h0], c1 = sC[h0 + 1];
                float w0 = sW[h0], w1 = sW[h0 + 1];
#define FTANH(x) ({ float _x = (x); float _a = fabsf(_x);                        \
                    float _t = 1.f - __fdividef(2.f, __expf(_a + _a) + 1.f);     \
                    copysignf(_t, _x); })
                sl = fmaf(FTANH(acc[mt][nt][0] + c0), w0, sl);
                sl = fmaf(FTANH(acc[mt][nt][1] + c1), w1, sl);
                sh = fmaf(FTANH(acc[mt][nt][2] + c0), w0, sh);
                sh = fmaf(FTANH(acc[mt][nt][3] + c1), w1, sh);
#undef FTANH
            }
            sl += __shfl_xor_sync(0xffffffffu, sl, 1);
            sl += __shfl_xor_sync(0xffffffffu, sl, 2);
            sh += __shfl_xor_sync(0xffffffffu, sh, 1);
            sh += __shfl_xor_sync(0xffffffffu, sh, 2);
            if ((lane & 3) == 0) {
                int r = mw * 32 + mt * 16 + (lane >> 2);
                red[r * 4 + nw]       = sl;
                red[(r + 8) * 4 + nw] = sh;
            }
        }
        __syncthreads();
        if (tid < MT) {
            float s = red[tid * 4] + red[tid * 4 + 1] + red[tid * 4 + 2] + red[tid * 4 + 3];
            g_logit[b * S_ + s0 + tid] = s;  // bo omitted: softmax shift-invariant
        }
    }
}

// ---------------- 3. softmax over S per batch -> p (1024 threads) ----------------
__global__ void softmax_kernel(float* __restrict__ p_out) {
    __shared__ float sred[32];
    __shared__ float sbcast;
    const int b = blockIdx.x, tid = threadIdx.x;

    float mx = -1e30f;
    for (int s = tid; s < S_; s += 1024) mx = fmaxf(mx, g_logit[b * S_ + s]);
#pragma unroll
    for (int o = 16; o; o >>= 1) mx = fmaxf(mx, __shfl_xor_sync(0xffffffffu, mx, o));
    if ((tid & 31) == 0) sred[tid >> 5] = mx;
    __syncthreads();
    if (tid < 32) {
        float v = sred[tid];
#pragma unroll
        for (int o = 16; o; o >>= 1) v = fmaxf(v, __shfl_xor_sync(0xffffffffu, v, o));
        if (tid == 0) sbcast = v;
    }
    __syncthreads();
    mx = sbcast;
    __syncthreads();

    float sum = 0.f;
    for (int s = tid; s < S_; s += 1024) {
        float e = expf(g_logit[b * S_ + s] - mx);
        g_logit[b * S_ + s] = e;
        sum += e;
    }
#pragma unroll
    for (int o = 16; o; o >>= 1) sum += __shfl_xor_sync(0xffffffffu, sum, o);
    if ((tid & 31) == 0) sred[tid >> 5] = sum;
    __syncthreads();
    if (tid < 32) {
        float v = sred[tid];
#pragma unroll
        for (int o = 16; o; o >>= 1) v += __shfl_xor_sync(0xffffffffu, v, o);
        if (tid == 0) sbcast = v;
    }
    __syncthreads();
    float inv = 1.f / sbcast;
    for (int s = tid; s < S_; s += 1024) p_out[b * S_ + s] = g_logit[b * S_ + s] * inv;
}

// ---------------- 4. out[b,:] = sum_s p[b,s] * v[s,b,:]  (float4, deep MLP) ------
__global__ void wsum_kernel(const float* __restrict__ v, const float* __restrict__ p) {
    const int b = blockIdx.y, sp = blockIdx.x, tid = threadIdx.x;  // 128 threads
    const int col = tid * 4;
    const int SCH = S_ / NSPLIT;  // 64
    const int s0 = sp * SCH;
    const float* pb = p + b * S_;
    float4 acc = make_float4(0.f, 0.f, 0.f, 0.f);
#pragma unroll 8
    for (int i = 0; i < SCH; i++) {
        int s = s0 + i;
        float pv = __ldg(pb + s);
        float4 vv = *(const float4*)(v + ((size_t)s * B_ + b) * V_ + col);
        acc.x = fmaf(pv, vv.x, acc.x);
        acc.y = fmaf(pv, vv.y, acc.y);
        acc.z = fmaf(pv, vv.z, acc.z);
        acc.w = fmaf(pv, vv.w, acc.w);
    }
    *(float4*)(g_part + (b * NSPLIT + sp) * V_ + col) = acc;
}

__global__ void reduce_out(float* __restrict__ out) {
    const int b = blockIdx.x, tid = threadIdx.x;  // 512 threads
    float s = 0.f;
#pragma unroll
    for (int i = 0; i < NSPLIT; i++) s += g_part[(b * NSPLIT + i) * V_ + tid];
    out[b * V_ + tid] = s;
}

// ---------------- launch ----------------
extern "C" void kernel_launch(void* const* d_in, const int* in_sizes, int n_in,
                              void* d_out, int out_size) {
    const float* q  = (const float*)d_in[0];
    const float* k  = (const float*)d_in[1];
    const float* v  = (const float*)d_in[2];
    const float* Wk = (const float*)d_in[3];
    const float* bk = (const float*)d_in[4];
    const float* Wq = (const float*)d_in[5];
    const float* bq = (const float*)d_in[6];
    const float* Wo = (const float*)d_in[7];
    // d_in[8] = bo: irrelevant under softmax shift invariance

    float* out = (float*)d_out;    // out[1,B,V]
    float* p   = out + B_ * V_;    // p[B,S]

    cudaFuncSetAttribute(logit_kernel, cudaFuncAttributeMaxDynamicSharedMemorySize, SMEM_TOTAL);

    prep_kernel<<<512 + B_, 256>>>(Wk, q, Wq, bq, bk);
    logit_kernel<<<dim3(S_ / MT, B_), THREADS, SMEM_TOTAL>>>(k, Wo);
    softmax_kernel<<<B_, 1024>>>(p);
    wsum_kernel<<<dim3(NSPLIT, B_), 128>>>(v, p);
    reduce_out<<<B_, V_>>>(out);
}